// round 8
// baseline (speedup 1.0000x reference)
#include <cuda_runtime.h>
#include <math.h>

#define NN      256      // neurons
#define NSAMP   512      // samples
#define NROUND  32       // MAX_SPIKES rounds
#define NSTEP   32       // RK4 steps per round

// flattened output offsets (all float32)
#define OUT_TIMES 0
#define OUT_VALS  (NSAMP * NROUND)                       // 16384
#define OUT_MARKS (OUT_VALS + NSAMP * NROUND * NN * 3)   // 12599296

// coefficient triple: value = .v * v0 + .i * i0 + .c * icn
struct C3 { float v, i, c; };
__device__ __forceinline__ C3 c3(float a, float b, float c) { return {a, b, c}; }
__device__ __forceinline__ C3 add(C3 a, C3 b) { return {a.v + b.v, a.i + b.i, a.c + b.c}; }
__device__ __forceinline__ C3 sub(C3 a, C3 b) { return {a.v - b.v, a.i - b.i, a.c - b.c}; }
__device__ __forceinline__ C3 scl(float s, C3 a) { return {s * a.v, s * a.i, s * a.c}; }

__device__ __forceinline__ float fast_sigmoid(float x) {
    // 1/(1+exp(-x)) via MUFU.EX2 + MUFU.RCP
    float e = __expf(-x);
    return __fdividef(1.0f, 1.0f + e);
}

__global__ __launch_bounds__(NN)
void snn_kernel(const float* __restrict__ ic,      // [256]
                const float* __restrict__ w,       // [256,256]
                const float* __restrict__ mu,      // [2]
                const float* __restrict__ v0g,     // [256]
                const float* __restrict__ i0g,     // [256]
                const float* __restrict__ s0g,     // [512,256]
                const float* __restrict__ reset_s, // [32,512,256]
                const int*   __restrict__ t1p,     // scalar
                float* __restrict__ out)
{
    const int samp = blockIdx.x;
    const int n    = threadIdx.x;
    const int lane = n & 31;
    const int wid  = n >> 5;

    __shared__ float sh_v[8], sh_p[8];
    __shared__ int   sh_i[8], sh_m[8];
    __shared__ float sh_frac, sh_tev;
    __shared__ int   sh_eidx;

    const float t1f = (float)(*t1p);
    const float mu1 = mu[0];
    const float mu2 = mu[1];
    const float icn = ic[n];

    float v  = v0g[n];
    float iC = i0g[n];
    float s  = s0g[samp * NN + n];
    float t0s = 0.0f;

    for (int k = 0; k < NROUND; ++k) {
        const float dt = (t1f - t0s) * (1.0f / (float)NSTEP);

        // prefetch the reset row for this round off the critical path
        const float rsk = reset_s[(size_t)k * NSAMP * NN + samp * NN + n];

        bool  done = false;
        float tev  = t1f;
        float yv = v, yi = iC, ys = s;
        bool  em = false;

        if (dt > 0.0f) {
            const float h  = dt;
            const float hh = 0.5f * h;
            const float h6 = h * (1.0f / 6.0f);

            // ---- per-round affine RK4 stage coefficients (thread-uniform) ----
            // basis: (v, i, icn).  dv = mu1*(i + icn - v), di = -mu2*i
            const C3 V   = c3(1.f, 0.f, 0.f);
            const C3 I   = c3(0.f, 1.f, 0.f);
            const C3 ONE = c3(0.f, 0.f, 1.f);
            C3 k1v = scl(mu1, sub(add(I, ONE), V));
            C3 k1i = scl(-mu2, I);
            C3 v2c = add(V, scl(hh, k1v));
            C3 i2c = add(I, scl(hh, k1i));
            C3 k2v = scl(mu1, sub(add(i2c, ONE), v2c));
            C3 k2i = scl(-mu2, i2c);
            C3 v3c = add(V, scl(hh, k2v));
            C3 i3c = add(I, scl(hh, k2i));
            C3 k3v = scl(mu1, sub(add(i3c, ONE), v3c));
            C3 k3i = scl(-mu2, i3c);
            C3 v4c = add(V, scl(h, k3v));
            C3 i4c = add(I, scl(h, k3i));
            C3 k4v = scl(mu1, sub(add(i4c, ONE), v4c));
            C3 k4i = scl(-mu2, i4c);
            C3 vnc = add(V, scl(h6, add(add(k1v, k4v), scl(2.f, add(k2v, k3v)))));
            C3 inc = add(I, scl(h6, add(add(k1i, k4i), scl(2.f, add(k2i, k3i)))));
            // fold per-thread icn into constants
            const float v2cc = v2c.c * icn, v3cc = v3c.c * icn;
            const float v4cc = v4c.c * icn, vncc = vnc.c * icn;
            const float pin  = inc.i;   // in2 = pin * iC  (inc.v == inc.c == 0)

            float tcur = t0s;
            // s is strictly monotone increasing within a round (ds>0, h>0),
            // so "crossed by step B" == "crossed at step A or B": check the
            // trigger once per TWO RK4 steps.
            for (int pr = 0; pr < NSTEP / 2; ++pr) {
                // ---- step A ----
                float v2a = fmaf(v2c.v, v, fmaf(v2c.i, iC, v2cc));
                float v3a = fmaf(v3c.v, v, fmaf(v3c.i, iC, v3cc));
                float v4a = fmaf(v4c.v, v, fmaf(v4c.i, iC, v4cc));
                float vA  = fmaf(vnc.v, v, fmaf(vnc.i, iC, vncc));
                float iA  = pin * iC;
                float dA1 = fast_sigmoid(v);
                float dA2 = fast_sigmoid(v2a);
                float dA3 = fast_sigmoid(v3a);
                float dA4 = fast_sigmoid(v4a);
                float sA  = fmaf(h6, (dA1 + dA4) + 2.0f * (dA2 + dA3), s);
                // ---- step B ----
                float v2b = fmaf(v2c.v, vA, fmaf(v2c.i, iA, v2cc));
                float v3b = fmaf(v3c.v, vA, fmaf(v3c.i, iA, v3cc));
                float v4b = fmaf(v4c.v, vA, fmaf(v4c.i, iA, v4cc));
                float vB  = fmaf(vnc.v, vA, fmaf(vnc.i, iA, vncc));
                float iB  = pin * iA;
                float dB1 = fast_sigmoid(vA);
                float dB2 = fast_sigmoid(v2b);
                float dB3 = fast_sigmoid(v3b);
                float dB4 = fast_sigmoid(v4b);
                float sB  = fmaf(h6, (dB1 + dB4) + 2.0f * (dB2 + dB3), sA);

                // ---- one BAR.RED per pair ----
                const int trig2 = __syncthreads_or(sB > 0.0f);
                if (!trig2) {
                    v = vB; iC = iB; s = sB;
                    tcur += 2.0f * dt;
                    continue;
                }

                // crossing happened at step A or B; disambiguate (once/round)
                const int trigA = __syncthreads_or(sA > 0.0f);
                float sp_l, sn_l, bv, bi, bs, nv, ni, ns, tbase;
                if (trigA) {
                    sp_l = s;  sn_l = sA;
                    bv = v;  bi = iC; bs = s;
                    nv = vA; ni = iA; ns = sA;
                    tbase = tcur;
                } else {
                    sp_l = sA; sn_l = sB;
                    bv = vA; bi = iA; bs = sA;
                    nv = vB; ni = iB; ns = sB;
                    tbase = tcur + dt;
                }

                // ---- fused argmax(sn_l) with payload (sp_l, idx; ties -> lower
                //      idx) + min index where sn_l > 0 ----
                {
                    float rv = sn_l, rp = sp_l;
                    int   ri = n;
                    int   rm = (sn_l > 0.0f) ? n : NN;
                    #pragma unroll
                    for (int o = 16; o > 0; o >>= 1) {
                        float ov = __shfl_down_sync(0xffffffffu, rv, o);
                        float op = __shfl_down_sync(0xffffffffu, rp, o);
                        int   oi = __shfl_down_sync(0xffffffffu, ri, o);
                        int   om = __shfl_down_sync(0xffffffffu, rm, o);
                        if (ov > rv || (ov == rv && oi < ri)) { rv = ov; rp = op; ri = oi; }
                        rm = min(rm, om);
                    }
                    if (lane == 0) { sh_v[wid] = rv; sh_p[wid] = rp; sh_i[wid] = ri; sh_m[wid] = rm; }
                    __syncthreads();
                    if (wid == 0) {
                        float rv2 = (lane < 8) ? sh_v[lane] : -INFINITY;
                        float rp2 = (lane < 8) ? sh_p[lane] : 0.0f;
                        int   ri2 = (lane < 8) ? sh_i[lane] : NN;
                        int   rm2 = (lane < 8) ? sh_m[lane] : NN;
                        #pragma unroll
                        for (int o = 4; o > 0; o >>= 1) {
                            float ov = __shfl_down_sync(0xffffffffu, rv2, o);
                            float op = __shfl_down_sync(0xffffffffu, rp2, o);
                            int   oi = __shfl_down_sync(0xffffffffu, ri2, o);
                            int   om = __shfl_down_sync(0xffffffffu, rm2, o);
                            if (ov > rv2 || (ov == rv2 && oi < ri2)) { rv2 = ov; rp2 = op; ri2 = oi; }
                            rm2 = min(rm2, om);
                        }
                        if (lane == 0) {
                            float frac = rp2 / (rp2 - rv2 + 1e-12f);
                            frac = fminf(fmaxf(frac, 0.0f), 1.0f);
                            sh_frac = frac;
                            sh_tev  = tbase + frac * dt;
                            sh_eidx = rm2;
                        }
                    }
                    __syncthreads();
                }

                const float frac = sh_frac;
                tev = sh_tev;
                v  = bv + frac * (nv - bv);
                iC = bi + frac * (ni - bi);
                s  = bs + frac * (ns - bs);
                yv = v; yi = iC; ys = s;
                em = (sn_l > 0.0f);
                done = true;
                break;
            }
            if (!done) { yv = v; yi = iC; ys = s; tev = t1f; }
        }

        const int eidx = done ? sh_eidx : 0;   // clamp for safe load
        const float wrow = done ? w[eidx * NN + n] : 0.0f;

        // ---- outputs for this round ----
        if (n == 0) out[OUT_TIMES + samp * NROUND + k] = tev;
        {
            float* vp = out + OUT_VALS + ((size_t)(samp * NROUND + k) * NN + n) * 3;
            vp[0] = yv; vp[1] = yi; vp[2] = ys;
            out[OUT_MARKS + (size_t)(samp * NROUND + k) * NN + n] = em ? 1.0f : 0.0f;
        }

        // ---- reset for next round ----
        v  = yv - (em ? 1.0f : 0.0f);
        iC = yi + wrow;
        float srs = em ? rsk : ys;
        s  = fminf(srs, 0.0f);
        t0s = tev;

        // NOTE: no trailing __syncthreads needed. Every write to sh_* in the
        // next round is preceded by at least one __syncthreads_or (a full
        // barrier), which orders this round's sh_eidx/sh_frac/sh_tev reads
        // before them. Rounds with dt==0 perform no sh_* writes at all.
    }
}

extern "C" void kernel_launch(void* const* d_in, const int* in_sizes, int n_in,
                              void* d_out, int out_size) {
    const float* ic      = (const float*)d_in[0];  // input_current [256]
    const float* w       = (const float*)d_in[1];  // w [256,256]
    const float* mu      = (const float*)d_in[2];  // mu [2]
    const float* v0      = (const float*)d_in[3];  // v0 [256]
    const float* i0      = (const float*)d_in[4];  // i0 [256]
    const float* s0      = (const float*)d_in[5];  // s0 [512,256]
    const float* reset_s = (const float*)d_in[6];  // reset_s [32,512,256]
    const int*   t1      = (const int*)d_in[7];    // t1 scalar
    float* out = (float*)d_out;

    (void)in_sizes; (void)n_in; (void)out_size;
    snn_kernel<<<NSAMP, NN>>>(ic, w, mu, v0, i0, s0, reset_s, t1, out);
}

// round 10
// speedup vs baseline: 1.5699x; 1.5699x over previous
#include <cuda_runtime.h>
#include <math.h>

#define NN      256      // neurons
#define NSAMP   512      // samples
#define NROUND  32       // MAX_SPIKES rounds
#define NSTEP   32       // RK4 steps per round
#define NPER    8        // neurons per thread
#define WPB     4        // warps (= samples) per block

// flattened output offsets (all float32)
#define OUT_TIMES 0
#define OUT_VALS  (NSAMP * NROUND)                       // 16384
#define OUT_MARKS (OUT_VALS + NSAMP * NROUND * NN * 3)   // 12599296

// coefficient triple: value = .v * v0 + .i * i0 + .c * icn
struct C3 { float v, i, c; };
__device__ __forceinline__ C3 c3(float a, float b, float c) { return {a, b, c}; }
__device__ __forceinline__ C3 add(C3 a, C3 b) { return {a.v + b.v, a.i + b.i, a.c + b.c}; }
__device__ __forceinline__ C3 sub(C3 a, C3 b) { return {a.v - b.v, a.i - b.i, a.c - b.c}; }
__device__ __forceinline__ C3 scl(float s, C3 a) { return {s * a.v, s * a.i, s * a.c}; }

__device__ __forceinline__ float fast_sigmoid(float x) {
    // 1/(1+exp(-x)) via MUFU.EX2 + MUFU.RCP
    float e = __expf(-x);
    return __fdividef(1.0f, 1.0f + e);
}

__global__ __launch_bounds__(WPB * 32)
void snn_kernel(const float* __restrict__ ic,      // [256]
                const float* __restrict__ w,       // [256,256]
                const float* __restrict__ mu,      // [2]
                const float* __restrict__ v0g,     // [256]
                const float* __restrict__ i0g,     // [256]
                const float* __restrict__ s0g,     // [512,256]
                const float* __restrict__ reset_s, // [32,512,256]
                const int*   __restrict__ t1p,     // scalar
                float* __restrict__ out)
{
    const int lane = threadIdx.x & 31;
    const int wid  = threadIdx.x >> 5;
    const int samp = blockIdx.x * WPB + wid;   // one warp == one sample

    const float t1f = (float)(*t1p);
    const float mu1 = mu[0];
    const float mu2 = mu[1];

    // thread owns neurons lane + 32*j  (coalesced everywhere)
    float v[NPER], iC[NPER], s[NPER], icn[NPER];
    #pragma unroll
    for (int j = 0; j < NPER; ++j) {
        const int n = lane + 32 * j;
        icn[j] = ic[n];
        v[j]   = v0g[n];
        iC[j]  = i0g[n];
        s[j]   = s0g[samp * NN + n];
    }
    float t0s = 0.0f;

    for (int k = 0; k < NROUND; ++k) {
        const float dt = (t1f - t0s) * (1.0f / (float)NSTEP);

        // prefetch the reset row for this round off the critical path
        float rsk[NPER];
        #pragma unroll
        for (int j = 0; j < NPER; ++j)
            rsk[j] = reset_s[(size_t)k * NSAMP * NN + samp * NN + lane + 32 * j];

        bool     done = false;
        float    tev  = t1f;
        unsigned emk  = 0;        // per-j spike mask
        int      eidx = 0;

        if (dt > 0.0f) {
            const float h  = dt;
            const float hh = 0.5f * h;
            const float h6 = h * (1.0f / 6.0f);

            // ---- per-round affine RK4 stage coefficients (warp-uniform) ----
            // basis: (v, i, icn).  dv = mu1*(i + icn - v), di = -mu2*i
            const C3 V   = c3(1.f, 0.f, 0.f);
            const C3 I   = c3(0.f, 1.f, 0.f);
            const C3 ONE = c3(0.f, 0.f, 1.f);
            C3 k1v = scl(mu1, sub(add(I, ONE), V));
            C3 k1i = scl(-mu2, I);
            C3 v2c = add(V, scl(hh, k1v));
            C3 i2c = add(I, scl(hh, k1i));
            C3 k2v = scl(mu1, sub(add(i2c, ONE), v2c));
            C3 k2i = scl(-mu2, i2c);
            C3 v3c = add(V, scl(hh, k2v));
            C3 i3c = add(I, scl(hh, k2i));
            C3 k3v = scl(mu1, sub(add(i3c, ONE), v3c));
            C3 k3i = scl(-mu2, i3c);
            C3 v4c = add(V, scl(h, k3v));
            C3 i4c = add(I, scl(h, k3i));
            C3 k4v = scl(mu1, sub(add(i4c, ONE), v4c));
            C3 k4i = scl(-mu2, i4c);
            C3 vnc = add(V, scl(h6, add(add(k1v, k4v), scl(2.f, add(k2v, k3v)))));
            C3 inc = add(I, scl(h6, add(add(k1i, k4i), scl(2.f, add(k2i, k3i)))));
            const float pin = inc.i;   // in2 = pin * iC

            // fold per-neuron icn into per-stage constants
            float v2cc[NPER], v3cc[NPER], v4cc[NPER], vncc[NPER];
            #pragma unroll
            for (int j = 0; j < NPER; ++j) {
                v2cc[j] = v2c.c * icn[j];
                v3cc[j] = v3c.c * icn[j];
                v4cc[j] = v4c.c * icn[j];
                vncc[j] = vnc.c * icn[j];
            }

            float tcur = t0s;
            for (int st = 0; st < NSTEP; ++st) {
                // ---- RK4 step over 8 neurons (pure register ILP) ----
                float vn[NPER], in2[NPER], sn2[NPER];
                bool mine = false;
                #pragma unroll
                for (int j = 0; j < NPER; ++j) {
                    float v2 = fmaf(v2c.v, v[j], fmaf(v2c.i, iC[j], v2cc[j]));
                    float v3 = fmaf(v3c.v, v[j], fmaf(v3c.i, iC[j], v3cc[j]));
                    float v4 = fmaf(v4c.v, v[j], fmaf(v4c.i, iC[j], v4cc[j]));
                    vn[j]  = fmaf(vnc.v, v[j], fmaf(vnc.i, iC[j], vncc[j]));
                    in2[j] = pin * iC[j];
                    float d1 = fast_sigmoid(v[j]);
                    float d2 = fast_sigmoid(v2);
                    float d3 = fast_sigmoid(v3);
                    float d4 = fast_sigmoid(v4);
                    sn2[j] = fmaf(h6, (d1 + d4) + 2.0f * (d2 + d3), s[j]);
                    mine = mine || (sn2[j] > 0.0f);
                }

                // ---- trigger check: single warp vote, no barrier ----
                if (!__any_sync(0xffffffffu, mine)) {
                    #pragma unroll
                    for (int j = 0; j < NPER; ++j) { v[j] = vn[j]; iC[j] = in2[j]; s[j] = sn2[j]; }
                    tcur += dt;
                    continue;
                }

                // ---- trigger path (once per round) ----
                // local argmax over own 8 neurons (ascending j + strict > keeps
                // the lowest index on ties, matching jnp.argmax) + local min
                // index with sn2 > 0
                float rv = sn2[0], rp = s[0];
                int   ri = lane;
                int   rm = (sn2[0] > 0.0f) ? lane : NN;
                #pragma unroll
                for (int j = 1; j < NPER; ++j) {
                    const int n = lane + 32 * j;
                    if (sn2[j] > rv) { rv = sn2[j]; rp = s[j]; ri = n; }
                    if (sn2[j] > 0.0f) rm = min(rm, n);
                }
                // warp butterfly: every lane ends with the full result
                #pragma unroll
                for (int o = 16; o > 0; o >>= 1) {
                    float ov = __shfl_xor_sync(0xffffffffu, rv, o);
                    float op = __shfl_xor_sync(0xffffffffu, rp, o);
                    int   oi = __shfl_xor_sync(0xffffffffu, ri, o);
                    int   om = __shfl_xor_sync(0xffffffffu, rm, o);
                    if (ov > rv || (ov == rv && oi < ri)) { rv = ov; rp = op; ri = oi; }
                    rm = min(rm, om);
                }

                float fr = rp / (rp - rv + 1e-12f);
                fr   = fminf(fmaxf(fr, 0.0f), 1.0f);
                tev  = tcur + fr * dt;
                eidx = rm;
                #pragma unroll
                for (int j = 0; j < NPER; ++j) {
                    v[j]  = v[j]  + fr * (vn[j]  - v[j]);
                    iC[j] = iC[j] + fr * (in2[j] - iC[j]);
                    s[j]  = s[j]  + fr * (sn2[j] - s[j]);
                    if (sn2[j] > 0.0f) emk |= (1u << j);
                }
                done = true;
                break;
            }
        }

        // ---- outputs + reset for this round (state v/iC/s currently == yev) ----
        if (lane == 0) out[OUT_TIMES + samp * NROUND + k] = tev;
        const size_t base = (size_t)(samp * NROUND + k) * NN;
        #pragma unroll
        for (int j = 0; j < NPER; ++j) {
            const int n = lane + 32 * j;
            float* vp = out + OUT_VALS + (base + n) * 3;
            vp[0] = v[j]; vp[1] = iC[j]; vp[2] = s[j];
            const bool em = (emk >> j) & 1u;
            out[OUT_MARKS + base + n] = em ? 1.0f : 0.0f;
            const float wrow = done ? w[eidx * NN + n] : 0.0f;
            v[j]  = v[j] - (em ? 1.0f : 0.0f);
            iC[j] = iC[j] + wrow;
            const float srs = em ? rsk[j] : s[j];
            s[j]  = fminf(srs, 0.0f);
        }
        t0s = tev;
    }
}

extern "C" void kernel_launch(void* const* d_in, const int* in_sizes, int n_in,
                              void* d_out, int out_size) {
    const float* ic      = (const float*)d_in[0];  // input_current [256]
    const float* w       = (const float*)d_in[1];  // w [256,256]
    const float* mu      = (const float*)d_in[2];  // mu [2]
    const float* v0      = (const float*)d_in[3];  // v0 [256]
    const float* i0      = (const float*)d_in[4];  // i0 [256]
    const float* s0      = (const float*)d_in[5];  // s0 [512,256]
    const float* reset_s = (const float*)d_in[6];  // reset_s [32,512,256]
    const int*   t1      = (const int*)d_in[7];    // t1 scalar
    float* out = (float*)d_out;

    (void)in_sizes; (void)n_in; (void)out_size;
    snn_kernel<<<NSAMP / WPB, WPB * 32>>>(ic, w, mu, v0, i0, s0, reset_s, t1, out);
}